// round 11
// baseline (speedup 1.0000x reference)
#include <cuda_runtime.h>
#include <cuda_bf16.h>
#include <math.h>
#include <stdint.h>

#define V_   4
#define T_   4
#define NS_  100000
#define NH_  12288
#define E_   100000
#define H_   64
#define ET_  (V_ * T_)
// lrelu(y) = max(y, 0.01y) = 0.505*y + 0.495*|y|
#define C_A  0.505f
#define C_B  0.495f

// ---------------- scratch (static __device__, no allocation) ----------------
__device__ int    g_deg_out[ET_ * NS_];        // counts per (et, s)
__device__ int    g_deg_in [ET_ * NH_];        // counts per (et, n)
__device__ float  g_s      [ET_ * NH_ * T_];   // (et, n, t), t innermost (float4-aligned)
__device__ float4 g_xT     [V_ * NS_];         // xT[v][s] over t, nan-cleaned

// ---------------- packed f32x2 helpers ----------------
__device__ __forceinline__ unsigned long long pk2(float lo, float hi) {
    unsigned long long r;
    asm("mov.b64 %0, {%1, %2};" : "=l"(r) : "f"(lo), "f"(hi));
    return r;
}
__device__ __forceinline__ void upk2(unsigned long long v, float& lo, float& hi) {
    asm("mov.b64 {%0, %1}, %2;" : "=f"(lo), "=f"(hi) : "l"(v));
}
__device__ __forceinline__ unsigned long long fma2(unsigned long long a,
                                                   unsigned long long b,
                                                   unsigned long long c) {
    unsigned long long d;
    asm("fma.rn.f32x2 %0, %1, %2, %3;" : "=l"(d) : "l"(a), "l"(b), "l"(c));
    return d;
}

// ---------------- kernel 1: degrees (4 edges/thread) + x transpose, fused ----------------
// Both jobs need exactly ET_*E_/4 == V_*NS_ == 400,000 threads.
__global__ void k_deg_trans(const float* __restrict__ x,
                            const int4* __restrict__ src4,
                            const int4* __restrict__ dst4) {
    int i = blockIdx.x * blockDim.x + threadIdx.x;
    if (i >= ET_ * E_ / 4) return;

    // --- degree counts ---
    int et = (i * 4) / E_;                     // 4-aligned groups never straddle etypes
    int4 s = src4[i];
    int4 d = dst4[i];
    int* po = &g_deg_out[et * NS_];
    int* pi = &g_deg_in [et * NH_];
    atomicAdd(po + s.x, 1); atomicAdd(po + s.y, 1);
    atomicAdd(po + s.z, 1); atomicAdd(po + s.w, 1);
    atomicAdd(pi + d.x, 1); atomicAdd(pi + d.y, 1);
    atomicAdd(pi + d.z, 1); atomicAdd(pi + d.w, 1);

    // --- transpose x: [V,T,NS] -> xT[v][s] float4 over t, nan_to_num ---
    int v  = i / NS_;
    int sn = i - v * NS_;
    float a0 = x[(v * T_ + 0) * NS_ + sn];
    float a1 = x[(v * T_ + 1) * NS_ + sn];
    float a2 = x[(v * T_ + 2) * NS_ + sn];
    float a3 = x[(v * T_ + 3) * NS_ + sn];
    float4 r;
    r.x = isnan(a0) ? 0.0f : a0;
    r.y = isnan(a1) ? 0.0f : a1;
    r.z = isnan(a2) ? 0.0f : a2;
    r.w = isnan(a3) ? 0.0f : a3;
    g_xT[i] = r;
}

// ---------------- kernel 2: normalized scatter (4 edges/thread, batched MLP) ----------------
__device__ __forceinline__ void red_v4(float* p, float4 xv, float ns) {
    asm volatile("red.global.add.v4.f32 [%0], {%1, %2, %3, %4};"
                 :: "l"(p), "f"(xv.x * ns), "f"(xv.y * ns),
                    "f"(xv.z * ns), "f"(xv.w * ns) : "memory");
}

__global__ void k_scatter(const int4* __restrict__ src4,
                          const int4* __restrict__ dst4) {
    int i = blockIdx.x * blockDim.x + threadIdx.x;   // over ET_*E_/4
    if (i >= ET_ * E_ / 4) return;
    int et = (i * 4) / E_;
    int v  = et >> 2;
    int4 s = src4[i];
    int4 d = dst4[i];

    int dg0 = __ldg(&g_deg_out[et * NS_ + s.x]);
    int dg1 = __ldg(&g_deg_out[et * NS_ + s.y]);
    int dg2 = __ldg(&g_deg_out[et * NS_ + s.z]);
    int dg3 = __ldg(&g_deg_out[et * NS_ + s.w]);
    float4 x0 = __ldg(&g_xT[v * NS_ + s.x]);
    float4 x1 = __ldg(&g_xT[v * NS_ + s.y]);
    float4 x2 = __ldg(&g_xT[v * NS_ + s.z]);
    float4 x3 = __ldg(&g_xT[v * NS_ + s.w]);

    float n0 = rsqrtf(fmaxf((float)dg0, 1.0f));
    float n1 = rsqrtf(fmaxf((float)dg1, 1.0f));
    float n2 = rsqrtf(fmaxf((float)dg2, 1.0f));
    float n3 = rsqrtf(fmaxf((float)dg3, 1.0f));

    float* base = &g_s[et * NH_ * T_];
    red_v4(base + d.x * T_, x0, n0);
    red_v4(base + d.y * T_, x1, n1);
    red_v4(base + d.z * T_, x2, n2);
    red_v4(base + d.w * T_, x3, n3);
}

// ---------------- kernel 3: epilogue (packed f32x2, smem-staged z, W/b in regs) ----------------
// out[n,v,t,h] = sum_tp lrelu( z[et,n,t]*W[et,h] + b[et,h] ),  z = s * rsqrt(max(deg_in,1))
#define NPB 8
__global__ void __launch_bounds__(256) k_epilogue(const float4* __restrict__ W4,
                                                  const float4* __restrict__ b4,
                                                  float4* __restrict__ out4) {
    __shared__ float4 zsm[ET_ * NPB];

    int tx = threadIdx.x;
    int n0 = blockIdx.x * NPB;

    if (tx < ET_ * NPB) {
        int et = tx >> 3;
        int k  = tx & (NPB - 1);
        int n  = n0 + k;
        float nd = rsqrtf(fmaxf((float)__ldg(&g_deg_in[et * NH_ + n]), 1.0f));
        float4 sv = *(const float4*)&g_s[(et * NH_ + n) * T_];
        sv.x *= nd; sv.y *= nd; sv.z *= nd; sv.w *= nd;
        zsm[tx] = sv;
    }

    int q = tx & 15;
    int t = (tx >> 4) & 3;
    int v = tx >> 6;

    // hoist W/b as packed f32x2 pairs
    unsigned long long w01[T_], w23[T_], b01[T_], b23[T_];
#pragma unroll
    for (int tp = 0; tp < T_; tp++) {
        int et = v * T_ + tp;
        float4 w  = W4[et * (H_ / 4) + q];
        float4 bb = b4[et * (H_ / 4) + q];
        w01[tp] = pk2(w.x, w.y);  w23[tp] = pk2(w.z, w.w);
        b01[tp] = pk2(bb.x, bb.y); b23[tp] = pk2(bb.z, bb.w);
    }
    const unsigned long long CA = pk2(C_A, C_A);
    const unsigned long long CB = pk2(C_B, C_B);
    const unsigned long long ABSM = 0x7fffffff7fffffffULL;

    __syncthreads();

#pragma unroll
    for (int k = 0; k < NPB; k++) {
        unsigned long long acc01 = 0ULL, acc23 = 0ULL;   // packed {0,0}
#pragma unroll
        for (int tp = 0; tp < T_; tp++) {
            int et = v * T_ + tp;
            float sv = ((const float*)&zsm[et * NPB + k])[t];   // LDS broadcast
            unsigned long long sv2 = pk2(sv, sv);
            unsigned long long y01 = fma2(sv2, w01[tp], b01[tp]);
            unsigned long long y23 = fma2(sv2, w23[tp], b23[tp]);
            acc01 = fma2(CA, y01, acc01);
            acc23 = fma2(CA, y23, acc23);
            acc01 = fma2(CB, y01 & ABSM, acc01);
            acc23 = fma2(CB, y23 & ABSM, acc23);
        }
        float4 r;
        upk2(acc01, r.x, r.y);
        upk2(acc23, r.z, r.w);
        int n = n0 + k;
        out4[((n * V_ + v) * T_ + t) * (H_ / 4) + q] = r;       // coalesced
    }
}

// ---------------- launch ----------------
extern "C" void kernel_launch(void* const* d_in, const int* in_sizes, int n_in,
                              void* d_out, int out_size) {
    const float* x = (const float*)d_in[0];
    const float* W = (const float*)d_in[1];
    const float* b = (const float*)d_in[2];
    const int* src = (const int*)d_in[3];
    const int* dst = (const int*)d_in[4];

    // zero scratch via memset nodes (near-DRAM-speed, no kernel)
    void* p_deg_out; cudaGetSymbolAddress(&p_deg_out, g_deg_out);
    void* p_deg_in;  cudaGetSymbolAddress(&p_deg_in,  g_deg_in);
    void* p_s;       cudaGetSymbolAddress(&p_s,       g_s);
    cudaMemsetAsync(p_deg_out, 0, ET_ * NS_ * sizeof(int));
    cudaMemsetAsync(p_deg_in,  0, ET_ * NH_ * sizeof(int));
    cudaMemsetAsync(p_s,       0, ET_ * NH_ * T_ * sizeof(float));

    const int threads = 256;
    const int groups = ET_ * E_ / 4;   // == V_*NS_ == 400,000

    k_deg_trans<<<(groups + threads - 1) / threads, threads>>>(
        x, (const int4*)src, (const int4*)dst);

    k_scatter<<<(groups + threads - 1) / threads, threads>>>(
        (const int4*)src, (const int4*)dst);

    k_epilogue<<<NH_ / NPB, 256>>>(
        (const float4*)W, (const float4*)b, (float4*)d_out);
}